// round 3
// baseline (speedup 1.0000x reference)
#include <cuda_runtime.h>
#include <cstdint>
#include <math.h>

// ---------------- problem constants (fixed by setup_inputs) ----------------
#define ZDIM 256
#define HID  128
#define NL   6
#define BB   2
#define IMG  64
#define HW   (IMG*IMG)          // 4096
#define SS   12
#define NRAYS (BB*HW)           // 8192
#define NPTS  (NRAYS*SS)        // 98304
#define FP_DIM (NL*HID)         // 768

#define AS_STRIDE 132           // 128 + 4 pad

// zc = -1/tan(deg2rad(12)/2), computed in double
#define ZC (-9.514364454222587f)

// ---------------- device scratch (no allocations allowed) ------------------
__device__ float g_freqs[BB*FP_DIM];
__device__ float g_phases[BB*FP_DIM];
__device__ float g_points[NPTS*3];     // coarse world points
__device__ float g_zvals[NPTS];        // coarse z (with perturbation)
__device__ float g_dirs[NRAYS*3];      // world-space ray dirs
__device__ float g_rgbs_c[NPTS*4];     // coarse rgb+sigma
__device__ float g_finez[NPTS];        // fine z samples
__device__ float g_points_f[NPTS*3];   // fine world points
__device__ float g_rgbs_f[NPTS*4];     // fine rgb+sigma

// ---------------- Threefry-2x32-20 (matches JAX) ---------------------------
__host__ __device__ static inline void tf2x32(uint32_t k0, uint32_t k1,
                                              uint32_t& x0, uint32_t& x1) {
    uint32_t ks2 = k0 ^ k1 ^ 0x1BD11BDAu;
    x0 += k0; x1 += k1;
#define TF_RND(r) { x0 += x1; x1 = (x1 << (r)) | (x1 >> (32 - (r))); x1 ^= x0; }
    TF_RND(13) TF_RND(15) TF_RND(26) TF_RND(6)
    x0 += k1;  x1 += ks2 + 1u;
    TF_RND(17) TF_RND(29) TF_RND(16) TF_RND(24)
    x0 += ks2; x1 += k0 + 2u;
    TF_RND(13) TF_RND(15) TF_RND(26) TF_RND(6)
    x0 += k0;  x1 += k1 + 3u;
    TF_RND(17) TF_RND(29) TF_RND(16) TF_RND(24)
    x0 += k1;  x1 += ks2 + 4u;
    TF_RND(13) TF_RND(15) TF_RND(26) TF_RND(6)
    x0 += ks2; x1 += k0 + 5u;
#undef TF_RND
}

// JAX partitionable random bits: counter = 64-bit index (hi=0), bits = o0 ^ o1
__device__ static inline float jax_uniform(uint32_t k0, uint32_t k1, uint32_t idx) {
    uint32_t x0 = 0u, x1 = idx;
    tf2x32(k0, k1, x0, x1);
    uint32_t bits = x0 ^ x1;
    return __uint_as_float((bits >> 9) | 0x3f800000u) - 1.0f;
}

// ---------------- kernel 1: mapping network --------------------------------
__global__ void map_kernel(const float* __restrict__ z,
                           const float* __restrict__ w0, const float* __restrict__ b0,
                           const float* __restrict__ w1, const float* __restrict__ b1,
                           const float* __restrict__ w2, const float* __restrict__ b2) {
    __shared__ float sh[ZDIM];
    int b = blockIdx.x, t = threadIdx.x;
    sh[t] = z[b*ZDIM + t];
    __syncthreads();
    float acc = b0[t];
    for (int k = 0; k < ZDIM; k++) acc = fmaf(sh[k], w0[k*256 + t], acc);
    float v = (acc >= 0.f) ? acc : 0.2f*acc;
    __syncthreads(); sh[t] = v; __syncthreads();
    acc = b1[t];
    for (int k = 0; k < 256; k++) acc = fmaf(sh[k], w1[k*256 + t], acc);
    v = (acc >= 0.f) ? acc : 0.2f*acc;
    __syncthreads(); sh[t] = v; __syncthreads();
    for (int j = t; j < FP_DIM*2; j += 256) {
        float a = b2[j];
        for (int k = 0; k < 256; k++) a = fmaf(sh[k], w2[k*(FP_DIM*2) + j], a);
        if (j < FP_DIM) g_freqs[b*FP_DIM + j] = a*15.0f + 30.0f;
        else            g_phases[b*FP_DIM + (j - FP_DIM)] = a;
    }
}

// ---------------- kernel 2: ray generation + coarse points -----------------
__global__ void raygen_kernel(const float* __restrict__ c2w,
                              uint32_t kp0, uint32_t kp1) {
    int ray = blockIdx.x * blockDim.x + threadIdx.x;
    if (ray >= NRAYS) return;
    int b = ray / HW, r = ray % HW;
    int h = r / IMG, w = r % IMG;
    float x = -1.0f + w * (2.0f/63.0f);
    float y =  1.0f - h * (2.0f/63.0f);
    float n  = sqrtf(x*x + y*y + ZC*ZC);
    float dx = x/n, dy = y/n, dz = ZC/n;
    const float* M = c2w + b*16;
    g_dirs[ray*3+0] = M[0]*dx + M[1]*dy + M[2]*dz;
    g_dirs[ray*3+1] = M[4]*dx + M[5]*dy + M[6]*dz;
    g_dirs[ray*3+2] = M[8]*dx + M[9]*dy + M[10]*dz;
    const float spacing = (1.12f - 0.88f) / 11.0f;
    for (int s = 0; s < SS; s++) {
        int idx = ray*SS + s;
        float u   = jax_uniform(kp0, kp1, (uint32_t)idx);
        float off = (u - 0.5f) * spacing;
        float zv  = 0.88f + s*spacing + off;
        float px = dx*zv, py = dy*zv, pz = dz*zv;
        g_points[idx*3+0] = M[0]*px + M[1]*py + M[2]*pz  + M[3];
        g_points[idx*3+1] = M[4]*px + M[5]*py + M[6]*pz  + M[7];
        g_points[idx*3+2] = M[8]*px + M[9]*py + M[10]*pz + M[11];
        g_zvals[idx] = zv;
    }
}

// ---------------- kernel 3/5: fused SIREN forward ---------------------------
__global__ void __launch_bounds__(256, 1)
siren_kernel(int fine,
             const float* __restrict__ fw, const float* __restrict__ fb,
             const float* __restrict__ hw_, const float* __restrict__ hb,
             const float* __restrict__ ow, const float* __restrict__ ob) {
    extern __shared__ float sm[];
    float* As = sm;                       // [128][132] activations, k-major
    float* Bs = sm + 128*AS_STRIDE;       // [128][132] weights
    float* fr = sm + 2*128*AS_STRIDE;     // 128
    float* ph = fr + 128;                 // 128
    float* bi = ph + 128;                 // 128

    const float* pts  = fine ? g_points_f : g_points;
    float*       outr = fine ? g_rgbs_f   : g_rgbs_c;

    int tid = threadIdx.x;
    int tx = tid & 15, ty = tid >> 4;
    int m0 = blockIdx.x * 128;
    int batch = m0 / (HW*SS);
    const float* frq = g_freqs  + batch*FP_DIM;
    const float* phs = g_phases + batch*FP_DIM;

    int ncol[8], mrow[8];
#pragma unroll
    for (int j = 0; j < 8; j++) ncol[j] = (j < 4) ? (tx*4 + j) : (64 + tx*4 + (j-4));
#pragma unroll
    for (int i = 0; i < 8; i++) mrow[i] = (i < 4) ? (ty*4 + i) : (64 + ty*4 + (i-4));

    // ---- first layer: 3 -> 128 ----
    {
        float* ptsh = Bs;           // 384
        float* fwsh = Bs + 512;     // 384
        float* fbsh = Bs + 1024;    // 128
        for (int i = tid; i < 384; i += 256) ptsh[i] = pts[m0*3 + i];
        for (int i = tid; i < 384; i += 256) fwsh[i] = fw[i];
        if (tid < 128) { fbsh[tid] = fb[tid]; fr[tid] = frq[tid]; ph[tid] = phs[tid]; }
        __syncthreads();
#pragma unroll
        for (int j = 0; j < 8; j++) {
            int n = ncol[j];
            float w0v = fwsh[n], w1v = fwsh[128+n], w2v = fwsh[256+n];
            float bn = fbsh[n], fn = fr[n], pn = ph[n];
#pragma unroll
            for (int i = 0; i < 8; i++) {
                int m = mrow[i];
                float v = bn + ptsh[m*3]*w0v + ptsh[m*3+1]*w1v + ptsh[m*3+2]*w2v;
                As[n*AS_STRIDE + m] = sinf(fn*v + pn);
            }
        }
        __syncthreads();
    }

    // ---- hidden layers 1..5: 128 -> 128 with sin(freq*(xW+b)+phase) ----
    for (int l = 1; l < NL; l++) {
        const float* W = hw_ + (l-1)*HID*HID;
        for (int i = tid*4; i < HID*HID; i += 1024) {
            int k = i >> 7, n = i & 127;
            float4 v = *reinterpret_cast<const float4*>(W + i);
            *reinterpret_cast<float4*>(&Bs[k*AS_STRIDE + n]) = v;
        }
        if (tid < 128) {
            fr[tid] = frq[l*HID + tid];
            ph[tid] = phs[l*HID + tid];
            bi[tid] = hb[(l-1)*HID + tid];
        }
        __syncthreads();

        float acc[8][8];
#pragma unroll
        for (int i = 0; i < 8; i++)
#pragma unroll
            for (int j = 0; j < 8; j++) acc[i][j] = 0.f;

#pragma unroll 2
        for (int k = 0; k < HID; k++) {
            float4 a0 = *reinterpret_cast<const float4*>(&As[k*AS_STRIDE + ty*4]);
            float4 a1 = *reinterpret_cast<const float4*>(&As[k*AS_STRIDE + 64 + ty*4]);
            float4 b0 = *reinterpret_cast<const float4*>(&Bs[k*AS_STRIDE + tx*4]);
            float4 b1 = *reinterpret_cast<const float4*>(&Bs[k*AS_STRIDE + 64 + tx*4]);
            float a[8]  = {a0.x,a0.y,a0.z,a0.w,a1.x,a1.y,a1.z,a1.w};
            float bv[8] = {b0.x,b0.y,b0.z,b0.w,b1.x,b1.y,b1.z,b1.w};
#pragma unroll
            for (int i = 0; i < 8; i++)
#pragma unroll
                for (int j = 0; j < 8; j++) acc[i][j] = fmaf(a[i], bv[j], acc[i][j]);
        }
        __syncthreads();
#pragma unroll
        for (int j = 0; j < 8; j++) {
            int n = ncol[j];
            float fn = fr[n], pn = ph[n], bn = bi[n];
#pragma unroll
            for (int i = 0; i < 8; i++)
                As[n*AS_STRIDE + mrow[i]] = sinf(fn*(acc[i][j] + bn) + pn);
        }
        __syncthreads();
    }

    // ---- output layer: 128 -> 4, sigmoid on rgb ----
    {
        float* owsh = Bs;          // 512
        float* obsh = Bs + 512;    // 4
        for (int i = tid; i < 512; i += 256) owsh[i] = ow[i];
        if (tid < 4) obsh[tid] = ob[tid];
        __syncthreads();
        for (int t2 = tid; t2 < 512; t2 += 256) {
            int m = t2 >> 2, j = t2 & 3;
            float a = obsh[j];
            for (int k = 0; k < HID; k++)
                a = fmaf(As[k*AS_STRIDE + m], owsh[k*4 + j], a);
            if (j < 3) a = 1.0f / (1.0f + expf(-a));
            outr[(m0 + m)*4 + j] = a;
        }
    }
}

// ---------------- kernel 4: coarse integration + inverse-CDF sampling ------
__global__ void sample_kernel(const float* __restrict__ c2w,
                              uint32_t kq0, uint32_t kq1) {
    int ray = blockIdx.x * blockDim.x + threadIdx.x;
    if (ray >= NRAYS) return;
    int b = ray / HW;
    int base = ray * SS;

    float z[SS], sg[SS];
    for (int s = 0; s < SS; s++) {
        z[s]  = g_zvals[base + s];
        sg[s] = g_rgbs_c[(base + s)*4 + 3];
    }
    // fancy_integration weights
    float wgt[SS]; float T = 1.0f;
    for (int s = 0; s < SS; s++) {
        float d = (s < SS-1) ? (z[s+1] - z[s]) : 1e10f;
        float a = 1.0f - expf(-d * fmaxf(sg[s], 0.0f));
        wgt[s] = a * T;
        T *= (1.0f - a + 1e-10f);
    }
    // pdf over w[1..10] (+1e-5)
    float wq[SS-2]; float sum = 0.0f;
    for (int i = 0; i < SS-2; i++) { wq[i] = wgt[i+1] + 1e-5f; sum += wq[i]; }
    float cdf[SS-1]; cdf[0] = 0.0f; float c = 0.0f;
    for (int i = 0; i < SS-2; i++) { c += wq[i] / sum; cdf[i+1] = c; }
    float bins[SS-1];
    for (int i = 0; i < SS-1; i++) bins[i] = 0.5f * (z[i] + z[i+1]);

    float ox = c2w[b*16 + 3], oy = c2w[b*16 + 7], oz = c2w[b*16 + 11];
    float dx = g_dirs[ray*3+0], dy = g_dirs[ray*3+1], dz = g_dirs[ray*3+2];

    for (int j = 0; j < SS; j++) {
        float u = jax_uniform(kq0, kq1, (uint32_t)(ray*SS + j));
        int ind = SS-1;  // searchsorted 'right': first i with cdf[i] > u, else 11
        for (int i = 0; i < SS-1; i++) { if (cdf[i] > u) { ind = i; break; } }
        int below = ind - 1; if (below < 0) below = 0; if (below > SS-2) below = SS-2;
        int above = (ind > SS-2) ? (SS-2) : ind;
        float clo = cdf[below], chi = cdf[above];
        float blo = bins[below], bhi = bins[above];
        float den = chi - clo; if (den < 1e-8f) den = 1.0f;
        float fz = blo + (u - clo) / den * (bhi - blo);
        g_finez[base + j] = fz;
        g_points_f[(base + j)*3 + 0] = ox + dx*fz;
        g_points_f[(base + j)*3 + 1] = oy + dy*fz;
        g_points_f[(base + j)*3 + 2] = oz + dz*fz;
    }
}

// ---------------- kernel 6: merge-sort + final integration ------------------
__global__ void final_kernel(float* __restrict__ out) {
    int ray = blockIdx.x * blockDim.x + threadIdx.x;
    if (ray >= NRAYS) return;
    int b = ray / HW, r = ray % HW;
    int h = r / IMG, w = r % IMG;
    int base = ray * SS;

    float z[2*SS]; float4 c[2*SS];
    const float4* rf = reinterpret_cast<const float4*>(g_rgbs_f);
    const float4* rc = reinterpret_cast<const float4*>(g_rgbs_c);
    for (int s = 0; s < SS; s++) { z[s]      = g_finez[base+s]; c[s]      = rf[base+s]; }
    for (int s = 0; s < SS; s++) { z[SS+s]   = g_zvals[base+s]; c[SS+s]   = rc[base+s]; }

    // stable insertion sort by z (fine entries precede coarse on ties)
    for (int i = 1; i < 2*SS; i++) {
        float kz = z[i]; float4 kc = c[i];
        int j = i - 1;
        while (j >= 0 && z[j] > kz) { z[j+1] = z[j]; c[j+1] = c[j]; j--; }
        z[j+1] = kz; c[j+1] = kc;
    }

    float T = 1.0f, R = 0.f, G = 0.f, Bc = 0.f, D = 0.f;
    for (int s = 0; s < 2*SS; s++) {
        float d = (s < 2*SS-1) ? (z[s+1] - z[s]) : 1e10f;
        float a = 1.0f - expf(-d * fmaxf(c[s].w, 0.0f));
        float wt = a * T;
        T *= (1.0f - a + 1e-10f);
        R += wt * c[s].x; G += wt * c[s].y; Bc += wt * c[s].z; D += wt * z[s];
    }
    // pixels: (B,3,H,W), *2-1
    out[((b*3 + 0)*IMG + h)*IMG + w] = R  * 2.0f - 1.0f;
    out[((b*3 + 1)*IMG + h)*IMG + w] = G  * 2.0f - 1.0f;
    out[((b*3 + 2)*IMG + h)*IMG + w] = Bc * 2.0f - 1.0f;
    // depth = D * (-rays_d_cam.z)
    float x = -1.0f + w * (2.0f/63.0f);
    float y =  1.0f - h * (2.0f/63.0f);
    float n = sqrtf(x*x + y*y + ZC*ZC);
    out[BB*3*HW + ray] = D * (-(ZC/n));
}

// ---------------- launch ----------------------------------------------------
extern "C" void kernel_launch(void* const* d_in, const int* in_sizes, int n_in,
                              void* d_out, int out_size) {
    const float* z    = (const float*)d_in[0];
    const float* c2w  = (const float*)d_in[1];
    const float* mw0  = (const float*)d_in[2];
    const float* mb0  = (const float*)d_in[3];
    const float* mw1  = (const float*)d_in[4];
    const float* mb1  = (const float*)d_in[5];
    const float* mw2  = (const float*)d_in[6];
    const float* mb2  = (const float*)d_in[7];
    const float* fw   = (const float*)d_in[8];
    const float* fb   = (const float*)d_in[9];
    const float* hw_  = (const float*)d_in[10];
    const float* hb   = (const float*)d_in[11];
    const float* ow   = (const float*)d_in[12];
    const float* ob   = (const float*)d_in[13];
    float* out = (float*)d_out;

    // JAX: key = key(42) -> data (0, 42); split (partitionable/foldlike):
    //   k_pert = threefry((0,42), counter (0,0)); k_pdf = threefry((0,42), (0,1))
    uint32_t kp0, kp1, kq0, kq1;
    { uint32_t x0 = 0u, x1 = 0u; tf2x32(0u, 42u, x0, x1); kp0 = x0; kp1 = x1; }
    { uint32_t x0 = 0u, x1 = 1u; tf2x32(0u, 42u, x0, x1); kq0 = x0; kq1 = x1; }

    size_t smem = (size_t)(2*128*AS_STRIDE + 3*128) * sizeof(float);  // ~136.7 KB
    cudaFuncSetAttribute(siren_kernel, cudaFuncAttributeMaxDynamicSharedMemorySize,
                         (int)smem);

    map_kernel   <<<BB, 256>>>(z, mw0, mb0, mw1, mb1, mw2, mb2);
    raygen_kernel<<<NRAYS/256, 256>>>(c2w, kp0, kp1);
    siren_kernel <<<NPTS/128, 256, smem>>>(0, fw, fb, hw_, hb, ow, ob);
    sample_kernel<<<NRAYS/256, 256>>>(c2w, kq0, kq1);
    siren_kernel <<<NPTS/128, 256, smem>>>(1, fw, fb, hw_, hb, ow, ob);
    final_kernel <<<NRAYS/256, 256>>>(out);
}